// round 10
// baseline (speedup 1.0000x reference)
#include <cuda_runtime.h>
#include <cuda_fp16.h>

#define B_  4
#define T_  2048
#define D_  512
#define H_  8
#define HD_ 64
#define BH_ (B_*H_)   // 32

// Scratch (allocation-free rule: __device__ globals). All fp16.
__device__ __align__(16) __half g_Xh   [8192*512];   // x, fp16
__device__ __align__(16) __half g_WqkvT[1536*512];   // W_qkv^T  [n][k]
__device__ __align__(16) __half g_WoutT[512*512];    // W_out^T  [n][k]
__device__ __align__(16) __half g_Qh   [BH_*T_*HD_]; // [bh][t][d], pre-scaled 0.125
__device__ __align__(16) __half g_Kh   [BH_*T_*HD_]; // [bh][t][d]
__device__ __align__(16) __half g_Vh   [BH_*HD_*T_]; // [bh][dv][t]
__device__ __align__(16) __half g_Ah   [8192*512];   // attention out, fp16

__device__ __forceinline__ unsigned pack_h2(float x, float y) {
    __half2 h = __floats2half2_rn(x, y);
    return *(unsigned*)&h;
}
__device__ __forceinline__ float2 unpack_h2(unsigned u) {
    __half2 h = *(__half2*)&u;
    return __half22float2(h);
}

__device__ __forceinline__ void mma_f16(float* c, const unsigned* a, unsigned b0, unsigned b1) {
    asm volatile(
        "mma.sync.aligned.m16n8k16.row.col.f32.f16.f16.f32 "
        "{%0,%1,%2,%3},{%4,%5,%6,%7},{%8,%9},{%0,%1,%2,%3};"
        : "+f"(c[0]), "+f"(c[1]), "+f"(c[2]), "+f"(c[3])
        : "r"(a[0]), "r"(a[1]), "r"(a[2]), "r"(a[3]), "r"(b0), "r"(b1));
}

__device__ __forceinline__ void ldsm_x4(unsigned& r0, unsigned& r1,
                                        unsigned& r2, unsigned& r3, unsigned addr) {
    asm volatile("ldmatrix.sync.aligned.m8n8.x4.shared.b16 {%0,%1,%2,%3}, [%4];"
                 : "=r"(r0), "=r"(r1), "=r"(r2), "=r"(r3) : "r"(addr));
}

__device__ __forceinline__ void cp16(unsigned dst, const void* src) {
    asm volatile("cp.async.cg.shared.global [%0], [%1], 16;" :: "r"(dst), "l"(src));
}

// ---------------------------------------------------------------------------
// Pre-convert kernels
// ---------------------------------------------------------------------------
__global__ void conv_x_f16(const float* __restrict__ in)   // 8192*512 elements
{
    int i = (blockIdx.x * 256 + threadIdx.x) * 4;
    float4 v = *(const float4*)(in + i);
    __half2* o = (__half2*)(g_Xh + i);
    o[0] = __floats2half2_rn(v.x, v.y);
    o[1] = __floats2half2_rn(v.z, v.w);
}

template<int SEL>   // 0: W_qkv -> g_WqkvT ; 1: W_out -> g_WoutT
__global__ void transpose_w(const float* __restrict__ in, int R, int C)
{
    __half* outp = SEL ? (__half*)g_WoutT : (__half*)g_WqkvT;
    __shared__ float tile[32][33];
    int c0 = blockIdx.x * 32, r0 = blockIdx.y * 32;
    for (int i = threadIdx.y; i < 32; i += 8)
        tile[i][threadIdx.x] = in[(size_t)(r0 + i) * C + c0 + threadIdx.x];
    __syncthreads();
    for (int i = threadIdx.y; i < 32; i += 8)
        outp[(size_t)(c0 + i) * R + r0 + threadIdx.x] = __float2half(tile[threadIdx.x][i]);
}

// ===========================================================================
// fp16 mma GEMM: C[128x128] = A[128x512] * B^T (+bias). ldmatrix fragments.
// A [M][512] fp16, B [N][512] fp16 (pre-transposed). 256 thr = 8 warps
// (4m x 2n), warp tile 32x64, k-tile 32, 3-stage cp.async ring.
// Smem rows 40 halves (20 words): LDSM row banks {0,20,8,28,16,4,24,12} ok.
// ===========================================================================
#define AST_H (128*40)    // halves per stage
#define GEMM_SMEM (6*AST_H*2)   // 61440 B

template<int N_GL, int EPI, int ASRC, int BSRC>
__global__ __launch_bounds__(256, 2) void gemm_f16(
    const float* __restrict__ bias,
    float* __restrict__ out)
{
    const __half* A_gl = (ASRC == 0) ? (const __half*)g_Xh    : (const __half*)g_Ah;
    const __half* B_gl = (BSRC == 0) ? (const __half*)g_WqkvT : (const __half*)g_WoutT;

    extern __shared__ char dsm[];
    __half* Abuf = (__half*)dsm;            // [3][128][40]
    __half* Bbuf = (__half*)dsm + 3 * AST_H;

    int bm = blockIdx.y * 128, bn = blockIdx.x * 128;
    int tid = threadIdx.x;
    int w = tid >> 5, lane = tid & 31, g = lane >> 2, t4 = lane & 3;
    int wm = (w >> 1) * 32, wn = (w & 1) * 64;

    // ldmatrix per-lane addressing: matrix quad -> (row, k-col) offsets
    int lq = lane >> 3, lr = lane & 7;
    int lrow = (lq & 1) * 8 + lr;      // 0..15
    int lcol = (lq >> 1) * 8;          // 0 or 8 halves

    unsigned sA = (unsigned)__cvta_generic_to_shared(Abuf);
    unsigned sB = (unsigned)__cvta_generic_to_shared(Bbuf);

    int a_row = tid >> 1;             // 0..127 (A m-row and B n-row)
    int a_hc  = (tid & 1) * 16;       // halves 0 or 16

    auto issue_tile = [&](int kt) {
        int buf = kt - (kt / 3) * 3;
        int k0 = kt * 32;
        const __half* asrc = A_gl + (size_t)(bm + a_row) * 512 + k0 + a_hc;
        unsigned da = sA + (unsigned)(buf * AST_H + a_row * 40 + a_hc) * 2;
        cp16(da, asrc); cp16(da + 16, asrc + 8);
        const __half* bsrc = B_gl + (size_t)(bn + a_row) * 512 + k0 + a_hc;
        unsigned db = sB + (unsigned)(buf * AST_H + a_row * 40 + a_hc) * 2;
        cp16(db, bsrc); cp16(db + 16, bsrc + 8);
        asm volatile("cp.async.commit_group;");
    };

    float acc[2][8][4];
    #pragma unroll
    for (int mt = 0; mt < 2; mt++)
        #pragma unroll
        for (int nt = 0; nt < 8; nt++)
            #pragma unroll
            for (int c = 0; c < 4; c++) acc[mt][nt][c] = 0.0f;

    issue_tile(0);
    issue_tile(1);

    #pragma unroll 1
    for (int kt = 0; kt < 16; kt++) {
        int buf = kt - (kt / 3) * 3;
        if (kt < 15) {
            asm volatile("cp.async.wait_group 1;");
        } else {
            asm volatile("cp.async.wait_group 0;");
        }
        __syncthreads();
        if (kt + 2 < 16) issue_tile(kt + 2);

        unsigned sAs = sA + (unsigned)(buf * AST_H) * 2;
        unsigned sBs = sB + (unsigned)(buf * AST_H) * 2;

        #pragma unroll
        for (int ks = 0; ks < 2; ks++) {
            int k0h = ks * 16;
            unsigned af[2][4];
            #pragma unroll
            for (int mt = 0; mt < 2; mt++) {
                unsigned addr = sAs + (unsigned)((wm + mt * 16 + lrow) * 40 + k0h + lcol) * 2;
                ldsm_x4(af[mt][0], af[mt][1], af[mt][2], af[mt][3], addr);
            }
            #pragma unroll
            for (int ntp = 0; ntp < 4; ntp++) {
                unsigned b0, b1, b2, b3;
                unsigned addr = sBs + (unsigned)((wn + ntp * 16 + lrow) * 40 + k0h + lcol) * 2;
                ldsm_x4(b0, b1, b2, b3, addr);
                mma_f16(acc[0][2 * ntp],     af[0], b0, b2);
                mma_f16(acc[0][2 * ntp + 1], af[0], b1, b3);
                mma_f16(acc[1][2 * ntp],     af[1], b0, b2);
                mma_f16(acc[1][2 * ntp + 1], af[1], b1, b3);
            }
        }
    }

    // Epilogue
    #pragma unroll
    for (int mt = 0; mt < 2; mt++) {
        #pragma unroll
        for (int nt = 0; nt < 8; nt++) {
            #pragma unroll
            for (int c = 0; c < 4; c++) {
                int m = bm + wm + mt * 16 + g + ((c >> 1) ? 8 : 0);
                int n = bn + wn + nt * 8 + 2 * t4 + (c & 1);
                float v = acc[mt][nt][c] + bias[n];
                if (EPI == 0) {
                    out[(size_t)m * N_GL + n] = v;
                } else {
                    int b = m >> 11;
                    int t = m & (T_ - 1);
                    int which = n >> 9;     // 0=q, 1=k, 2=v
                    int r = n & 511;
                    int h = r >> 6, hd = r & 63;
                    int bh = b * H_ + h;
                    if (which == 0)
                        g_Qh[((size_t)bh * T_ + t) * HD_ + hd] = __float2half(v * 0.125f);
                    else if (which == 1)
                        g_Kh[((size_t)bh * T_ + t) * HD_ + hd] = __float2half(v);
                    else
                        g_Vh[((size_t)bh * HD_ + hd) * T_ + t] = __float2half(v);
                }
            }
        }
    }
}

// ---------------------------------------------------------------------------
// Flash attention (causal), fp16 mma + ldmatrix, cp.async double-buffered K/V.
// Grid: (qtile=16, bh=32). 256 threads = 8 warps; warp w owns Q rows
// [q0+16w, q0+16w+16). KV tiles of 64. K smem [j][d], V smem [dv][j],
// stride 72 halves (36 words): LDSM row banks {0,4,...,28} conflict-free.
// P chains register->A-frag; l summed from fp16-ROUNDED P.
// ---------------------------------------------------------------------------
#define KST_H (64*72)     // halves per K (or V) stage
#define ATTN_SMEM (4*KST_H*2)   // 36864 B

__global__ __launch_bounds__(256, 2) void attn_f16()
{
    extern __shared__ char dsm[];
    __half* Kbuf = (__half*)dsm;             // [2][64][72]
    __half* Vbuf = (__half*)dsm + 2 * KST_H; // [2][64][72]

    int qt = 15 - blockIdx.x;     // big tiles first (load balance)
    int bh = blockIdx.y;
    int tid = threadIdx.x;
    int w = tid >> 5, lane = tid & 31;
    int g = lane >> 2, t4 = lane & 3;
    int q0 = qt * 128;

    int lq = lane >> 3, lr = lane & 7;
    int lrow = (lq & 1) * 8 + lr;
    int lcol = (lq >> 1) * 8;

    const __half* Qp = g_Qh + (size_t)bh * T_ * HD_;
    const __half* Kp = g_Kh + (size_t)bh * T_ * HD_;
    const __half* Vp = g_Vh + (size_t)bh * HD_ * T_;

    unsigned k_smem = (unsigned)__cvta_generic_to_shared(Kbuf);
    unsigned v_smem = (unsigned)__cvta_generic_to_shared(Vbuf);

    int ld_row = tid >> 2;                // 0..63
    int ld_hc  = (tid & 3) * 16;          // halves 0,16,32,48

    int r0 = q0 + w * 16 + g;

    // Q fragments straight from gmem: 4 k16 steps x 4 half2 regs
    unsigned qa[4][4];
    #pragma unroll
    for (int ks = 0; ks < 4; ks++) {
        int k0 = ks * 16 + 2 * t4;
        qa[ks][0] = *(const unsigned*)&Qp[(size_t)r0 * HD_ + k0];
        qa[ks][1] = *(const unsigned*)&Qp[(size_t)(r0 + 8) * HD_ + k0];
        qa[ks][2] = *(const unsigned*)&Qp[(size_t)r0 * HD_ + k0 + 8];
        qa[ks][3] = *(const unsigned*)&Qp[(size_t)(r0 + 8) * HD_ + k0 + 8];
    }

    float O[8][4];
    #pragma unroll
    for (int n = 0; n < 8; n++)
        #pragma unroll
        for (int c = 0; c < 4; c++) O[n][c] = 0.0f;
    float m0 = -1e30f, m1 = -1e30f, l0 = 0.0f, l1 = 0.0f;

    int nkt = 2 * (qt + 1);

    auto issue_tile = [&](int kt) {
        int bb = kt & 1;
        int j0 = kt * 64;
        unsigned kb = k_smem + (unsigned)(bb * KST_H) * 2;
        unsigned vb = v_smem + (unsigned)(bb * KST_H) * 2;
        cp16(kb + (unsigned)(ld_row * 72 + ld_hc) * 2,
             Kp + (size_t)(j0 + ld_row) * HD_ + ld_hc);
        cp16(kb + (unsigned)(ld_row * 72 + ld_hc + 8) * 2,
             Kp + (size_t)(j0 + ld_row) * HD_ + ld_hc + 8);
        cp16(vb + (unsigned)(ld_row * 72 + ld_hc) * 2,
             Vp + (size_t)ld_row * T_ + j0 + ld_hc);
        cp16(vb + (unsigned)(ld_row * 72 + ld_hc + 8) * 2,
             Vp + (size_t)ld_row * T_ + j0 + ld_hc + 8);
        asm volatile("cp.async.commit_group;");
    };

    issue_tile(0);

    for (int kt = 0; kt < nkt; kt++) {
        int bb = kt & 1;
        if (kt + 1 < nkt) {
            issue_tile(kt + 1);
            asm volatile("cp.async.wait_group 1;");
        } else {
            asm volatile("cp.async.wait_group 0;");
        }
        __syncthreads();

        unsigned kbs = k_smem + (unsigned)(bb * KST_H) * 2;
        unsigned vbs = v_smem + (unsigned)(bb * KST_H) * 2;
        int j0 = kt * 64;

        // S = Q*K^T : 4 k16 steps, K-frags via ldmatrix (16 j-rows x 16 d)
        float S[8][4];
        #pragma unroll
        for (int n = 0; n < 8; n++)
            #pragma unroll
            for (int c = 0; c < 4; c++) S[n][c] = 0.0f;

        #pragma unroll
        for (int ks = 0; ks < 4; ks++) {
            int k0h = ks * 16;
            #pragma unroll
            for (int ntp = 0; ntp < 4; ntp++) {
                unsigned b0, b1, b2, b3;
                unsigned addr = kbs + (unsigned)((ntp * 16 + lrow) * 72 + k0h + lcol) * 2;
                ldsm_x4(b0, b1, b2, b3, addr);
                mma_f16(S[2 * ntp],     qa[ks], b0, b2);
                mma_f16(S[2 * ntp + 1], qa[ks], b1, b3);
            }
        }

        // Causal mask (only last two tiles can straddle the diagonal)
        if (kt >= nkt - 2) {
            int qi0 = r0, qi1 = r0 + 8;
            #pragma unroll
            for (int n = 0; n < 8; n++) {
                int j = j0 + 8 * n + 2 * t4;
                if (j     > qi0) S[n][0] = -1e30f;
                if (j + 1 > qi0) S[n][1] = -1e30f;
                if (j     > qi1) S[n][2] = -1e30f;
                if (j + 1 > qi1) S[n][3] = -1e30f;
            }
        }

        // Online softmax (rows r0 and r0+8; quad lanes share a row)
        float vmax0 = -1e30f, vmax1 = -1e30f;
        #pragma unroll
        for (int n = 0; n < 8; n++) {
            vmax0 = fmaxf(vmax0, fmaxf(S[n][0], S[n][1]));
            vmax1 = fmaxf(vmax1, fmaxf(S[n][2], S[n][3]));
        }
        vmax0 = fmaxf(vmax0, __shfl_xor_sync(0xffffffffu, vmax0, 1));
        vmax0 = fmaxf(vmax0, __shfl_xor_sync(0xffffffffu, vmax0, 2));
        vmax1 = fmaxf(vmax1, __shfl_xor_sync(0xffffffffu, vmax1, 1));
        vmax1 = fmaxf(vmax1, __shfl_xor_sync(0xffffffffu, vmax1, 2));

        float nm0 = fmaxf(m0, vmax0);
        float nm1 = fmaxf(m1, vmax1);
        float fac0 = __expf(m0 - nm0);
        float fac1 = __expf(m1 - nm1);
        m0 = nm0; m1 = nm1;

        // P = exp(S-m) -> fp16 A-fragments; l accumulates the ROUNDED p
        unsigned pa[8][2];
        float rs0 = 0.0f, rs1 = 0.0f;
        #pragma unroll
        for (int n = 0; n < 8; n++) {
            unsigned u0 = pack_h2(__expf(S[n][0] - nm0), __expf(S[n][1] - nm0));
            unsigned u1 = pack_h2(__expf(S[n][2] - nm1), __expf(S[n][3] - nm1));
            pa[n][0] = u0; pa[n][1] = u1;
            float2 f0 = unpack_h2(u0);
            float2 f1 = unpack_h2(u1);
            rs0 += f0.x + f0.y;
            rs1 += f1.x + f1.y;
        }
        rs0 += __shfl_xor_sync(0xffffffffu, rs0, 1);
        rs0 += __shfl_xor_sync(0xffffffffu, rs0, 2);
        rs1 += __shfl_xor_sync(0xffffffffu, rs1, 1);
        rs1 += __shfl_xor_sync(0xffffffffu, rs1, 2);
        l0 = l0 * fac0 + rs0;
        l1 = l1 * fac1 + rs1;

        #pragma unroll
        for (int n = 0; n < 8; n++) {
            O[n][0] *= fac0; O[n][1] *= fac0;
            O[n][2] *= fac1; O[n][3] *= fac1;
        }

        // O += P*V : V-frags via ldmatrix (16 dv-rows x 16 j)
        #pragma unroll
        for (int kk = 0; kk < 4; kk++) {
            unsigned a[4] = { pa[2 * kk][0], pa[2 * kk][1],
                              pa[2 * kk + 1][0], pa[2 * kk + 1][1] };
            #pragma unroll
            for (int ntp = 0; ntp < 4; ntp++) {
                unsigned b0, b1, b2, b3;
                unsigned addr = vbs + (unsigned)((ntp * 16 + lrow) * 72 + kk * 16 + lcol) * 2;
                ldsm_x4(b0, b1, b2, b3, addr);
                mma_f16(O[2 * ntp],     a, b0, b2);
                mma_f16(O[2 * ntp + 1], a, b1, b3);
            }
        }
        __syncthreads();   // all reads of buffer bb done before refill
    }

    // Epilogue: normalize, write g_Ah (fp16, feeds out-GEMM)
    int b = bh >> 3, h = bh & 7;
    float inv0 = 1.0f / l0;
    float inv1 = 1.0f / l1;
    #pragma unroll
    for (int n = 0; n < 8; n++) {
        int dv = 8 * n + 2 * t4;
        *(__half2*)&g_Ah[((size_t)b * T_ + r0) * D_ + h * HD_ + dv] =
            __floats2half2_rn(O[n][0] * inv0, O[n][1] * inv0);
        *(__half2*)&g_Ah[((size_t)b * T_ + r0 + 8) * D_ + h * HD_ + dv] =
            __floats2half2_rn(O[n][2] * inv1, O[n][3] * inv1);
    }
}

// ---------------------------------------------------------------------------
extern "C" void kernel_launch(void* const* d_in, const int* in_sizes, int n_in,
                              void* d_out, int out_size)
{
    const float* x     = (const float*)d_in[0];   // [4,2048,512]
    const float* W_qkv = (const float*)d_in[1];   // [512,1536]
    const float* b_qkv = (const float*)d_in[2];   // [1536]
    const float* W_out = (const float*)d_in[3];   // [512,512]
    const float* b_out = (const float*)d_in[4];   // [512]
    float* out = (float*)d_out;                   // [4,2048,512]

    cudaFuncSetAttribute(gemm_f16<1536, 1, 0, 0>,
                         cudaFuncAttributeMaxDynamicSharedMemorySize, GEMM_SMEM);
    cudaFuncSetAttribute(gemm_f16<512, 0, 1, 1>,
                         cudaFuncAttributeMaxDynamicSharedMemorySize, GEMM_SMEM);
    cudaFuncSetAttribute(attn_f16, cudaFuncAttributeMaxDynamicSharedMemorySize, ATTN_SMEM);

    conv_x_f16<<<4096, 256>>>(x);
    transpose_w<0><<<dim3(48, 16), dim3(32, 8)>>>(W_qkv, 512, 1536);
    transpose_w<1><<<dim3(16, 16), dim3(32, 8)>>>(W_out, 512, 512);
    gemm_f16<1536, 1, 0, 0><<<dim3(12, 64), 256, GEMM_SMEM>>>(b_qkv, nullptr);
    attn_f16<<<dim3(16, 32), 256, ATTN_SMEM>>>();
    gemm_f16<512, 0, 1, 1><<<dim3(4, 64), 256, GEMM_SMEM>>>(b_out, out);
}